// round 6
// baseline (speedup 1.0000x reference)
#include <cuda_runtime.h>
#include <math.h>

#define OUT_DIM 4096
#define DPC     16
#define NCOLS   (OUT_DIM * DPC)   // 65536
#define BATCH   512
#define NWARPS  8                 // warps per block; each warp = 32 windows

// Per-column boost factors, batch-invariant: computed once per launch.
__device__ float g_bf[NCOLS];

__global__ void bf_kernel(const float* __restrict__ duty_cycle,
                          const float* __restrict__ boost_strength) {
    int k = blockIdx.x * blockDim.x + threadIdx.x;
    const float td = (float)OUT_DIM / (float)NCOLS;  // 0.0625
    float bs = boost_strength[0];
    g_bf[k] = expf((td - duty_cycle[k]) * bs);
#if __CUDA_ARCH__ >= 900
    cudaTriggerProgrammaticLaunchCompletion();
#endif
}

__global__ void __launch_bounds__(256, 5)
dkw_kernel(const float* __restrict__ x, float* __restrict__ out) {
    // Per-warp private SMEM: 512 staged products (+pad) and 32 argmax indices.
    __shared__ float prod[NWARPS][520];
    __shared__ int   s_bj[NWARPS][32];

    const int lane = threadIdx.x & 31;
    const int wrp  = threadIdx.x >> 5;
    const int g = blockIdx.x * NWARPS + wrp;   // global warp id, 0..65535
    const int b = g >> 7;                      // batch row (128 warps per row)
    const int r = g & 127;                     // warp within row

    const size_t rowoff = (size_t)b * NCOLS;
    const int W0 = 480 * r;                    // window span start (16B aligned)
    const int O0 = 512 * r;                    // output chunk start
    // Over-fetch proof: W0 + 512 <= 480*127 + 512 = 61472 < 65536.

    const float4* xw4 = reinterpret_cast<const float4*>(x + rowoff + W0);
    const float4* xc4 = reinterpret_cast<const float4*>(x + rowoff + O0);
    const float4* bf4 = reinterpret_cast<const float4*>(g_bf + W0);

    // ---- Front-load all 12 LDG.128 (reg budget forced by launch_bounds) ----
    float4 xw[4], xc[4], bv[4];
#pragma unroll
    for (int k = 0; k < 4; ++k) xw[k] = xw4[lane + 32 * k];
#pragma unroll
    for (int k = 0; k < 4; ++k) xc[k] = xc4[lane + 32 * k];

#if __CUDA_ARCH__ >= 900
    cudaGridDependencySynchronize();           // g_bf ready (PDL)
#endif
#pragma unroll
    for (int k = 0; k < 4; ++k) bv[k] = bf4[lane + 32 * k];

    // ---- Stage boosted products into this warp's SMEM slice ----
    float4* p4 = reinterpret_cast<float4*>(prod[wrp]);
#pragma unroll
    for (int k = 0; k < 4; ++k) {
        float4 p;
        p.x = xw[k].x * bv[k].x;
        p.y = xw[k].y * bv[k].y;
        p.z = xw[k].z * bv[k].z;
        p.w = xw[k].w * bv[k].w;
        p4[lane + 32 * k] = p;
    }
    __syncwarp();

    // ---- Argmax: lane owns window (32g + lane); stride-15 LDS, conflict-free ----
    const float* ps = prod[wrp] + 15 * lane;   // 15*31+16 = 481 <= 512 staged
    float best = -INFINITY;
    int bj = 0;
#pragma unroll
    for (int j = 0; j < DPC; ++j) {
        float v = ps[j];
        if (v > best) { best = v; bj = j; }
    }
    s_bj[wrp][lane] = bj;
    __syncwarp();

    // ---- Masked store from registers: coalesced STG.128 ----
    float4* o4 = reinterpret_cast<float4*>(out + rowoff + O0);
#pragma unroll
    for (int k = 0; k < 4; ++k) {
        int f  = lane + 32 * k;                // float4 index 0..127 in chunk
        int c  = f >> 2;                       // window index within warp
        int j0 = (f & 3) << 2;                 // first j covered by this float4
        int bjc = s_bj[wrp][c];
        float4 v;
        v.x = (bjc == j0 + 0) ? xc[k].x : 0.0f;
        v.y = (bjc == j0 + 1) ? xc[k].y : 0.0f;
        v.z = (bjc == j0 + 2) ? xc[k].z : 0.0f;
        v.w = (bjc == j0 + 3) ? xc[k].w : 0.0f;
        o4[f] = v;
    }
}

extern "C" void kernel_launch(void* const* d_in, const int* in_sizes, int n_in,
                              void* d_out, int out_size) {
    const float* x  = (const float*)d_in[0];
    const float* dc = (const float*)d_in[1];
    const float* bs = (const float*)d_in[2];
    float* out = (float*)d_out;

    bf_kernel<<<NCOLS / 256, 256>>>(dc, bs);

    cudaLaunchConfig_t cfg = {};
    cfg.gridDim  = dim3(BATCH * OUT_DIM / (32 * NWARPS), 1, 1);   // 8192
    cfg.blockDim = dim3(32 * NWARPS, 1, 1);
    cfg.dynamicSmemBytes = 0;
    cfg.stream = 0;
    cudaLaunchAttribute attr[1];
    attr[0].id = cudaLaunchAttributeProgrammaticStreamSerialization;
    attr[0].val.programmaticStreamSerializationAllowed = 1;
    cfg.attrs = attr;
    cfg.numAttrs = 1;
    cudaLaunchKernelEx(&cfg, dkw_kernel, x, out);
}

// round 10
// speedup vs baseline: 1.2700x; 1.2700x over previous
#include <cuda_runtime.h>
#include <math.h>

#define OUT_DIM 4096
#define DPC     16
#define NCOLS   (OUT_DIM * DPC)   // 65536
#define BATCH   512
#define WPB     256               // windows (output chunks) per block
#define WSPAN4  961               // float4 count covering window span (3841 floats)

// Per-column boost factors, batch-invariant: computed once per launch.
__device__ float g_bf[NCOLS];

__global__ void bf_kernel(const float* __restrict__ duty_cycle,
                          const float* __restrict__ boost_strength) {
    int k = blockIdx.x * blockDim.x + threadIdx.x;
    const float td = (float)OUT_DIM / (float)NCOLS;  // 0.0625
    float bs = boost_strength[0];
    g_bf[k] = expf((td - duty_cycle[k]) * bs);
#if __CUDA_ARCH__ >= 900
    cudaTriggerProgrammaticLaunchCompletion();
#endif
}

__global__ void __launch_bounds__(256)
dkw_kernel(const float* __restrict__ x, float* __restrict__ out) {
    __shared__ float prod[WSPAN4 * 4];   // boosted window span
    __shared__ int   s_bj[WPB];

    const int tid = threadIdx.x;
    const int b = blockIdx.x >> 4;        // batch row (consecutive blocks share row)
    const int w = blockIdx.x & 15;        // window-block within row

    const size_t rowoff = (size_t)b * NCOLS;
    const int W0 = 3840 * w;              // window span start (16B aligned)
    const int O0 = 4096 * w;              // output chunk span start

#if __CUDA_ARCH__ >= 900
    cudaGridDependencySynchronize();      // g_bf ready (PDL)
#endif

    // ---- Stage boosted products: fully coalesced float4 loads ----
    const float4* xw4 = reinterpret_cast<const float4*>(x + rowoff + W0);
    const float4* bf4 = reinterpret_cast<const float4*>(g_bf + W0);
    float4* p4 = reinterpret_cast<float4*>(prod);
#pragma unroll
    for (int t = tid; t < WSPAN4; t += WPB) {
        float4 xv = xw4[t];
        float4 bv = bf4[t];
        float4 p;
        p.x = xv.x * bv.x;
        p.y = xv.y * bv.y;
        p.z = xv.z * bv.z;
        p.w = xv.w * bv.w;
        p4[t] = p;
    }
    __syncthreads();

    // ---- Argmax over window [15*tid, 15*tid+16): stride-15 LDS, conflict-free ----
    const int wb = 15 * tid;
    float best = -INFINITY;
    int bj = 0;
#pragma unroll
    for (int j = 0; j < DPC; ++j) {
        float v = prod[wb + j];
        if (v > best) { best = v; bj = j; }
    }
    s_bj[tid] = bj;
    __syncthreads();

    // ---- Output: coalesced re-read of x chunk (L1/L2 hot) + mask + STREAMING store ----
    // __stcs marks out lines evict-first so the 128MB output never displaces x
    // (x ~= L2 capacity; keeping it resident converts replay reads to L2 hits).
    const float4* xc4 = reinterpret_cast<const float4*>(x + rowoff + O0);
    float4* o4 = reinterpret_cast<float4*>(out + rowoff + O0);
#pragma unroll
    for (int q = 0; q < 4; ++q) {
        int f  = tid + WPB * q;           // float4 index 0..1023
        int c  = f >> 2;                  // window index within block
        int j0 = (f & 3) << 2;            // first j covered by this float4
        int bjc = s_bj[c];
        float4 xv = xc4[f];
        float4 v;
        v.x = (bjc == j0 + 0) ? xv.x : 0.0f;
        v.y = (bjc == j0 + 1) ? xv.y : 0.0f;
        v.z = (bjc == j0 + 2) ? xv.z : 0.0f;
        v.w = (bjc == j0 + 3) ? xv.w : 0.0f;
        __stcs(&o4[f], v);
    }
}

extern "C" void kernel_launch(void* const* d_in, const int* in_sizes, int n_in,
                              void* d_out, int out_size) {
    const float* x  = (const float*)d_in[0];
    const float* dc = (const float*)d_in[1];
    const float* bs = (const float*)d_in[2];
    float* out = (float*)d_out;

    bf_kernel<<<NCOLS / 256, 256>>>(dc, bs);

    cudaLaunchConfig_t cfg = {};
    cfg.gridDim  = dim3(BATCH * (OUT_DIM / WPB), 1, 1);
    cfg.blockDim = dim3(WPB, 1, 1);
    cfg.dynamicSmemBytes = 0;
    cfg.stream = 0;
    cudaLaunchAttribute attr[1];
    attr[0].id = cudaLaunchAttributeProgrammaticStreamSerialization;
    attr[0].val.programmaticStreamSerializationAllowed = 1;
    cfg.attrs = attr;
    cfg.numAttrs = 1;
    cudaLaunchKernelEx(&cfg, dkw_kernel, x, out);
}

// round 14
// speedup vs baseline: 1.2717x; 1.0013x over previous
#include <cuda_runtime.h>
#include <cuda_pipeline_primitives.h>
#include <math.h>

#define OUT_DIM 4096
#define DPC     16
#define NCOLS   (OUT_DIM * DPC)   // 65536
#define BATCH   512
#define WPB     256               // windows (output chunks) per block
#define NSTAGE4 964               // float4 per staged array (3856 floats >= 3841 needed)

// Per-column boost factors, batch-invariant: computed once per launch.
__device__ float g_bf[NCOLS];

__global__ void bf_kernel(const float* __restrict__ duty_cycle,
                          const float* __restrict__ boost_strength) {
    int k = blockIdx.x * blockDim.x + threadIdx.x;
    const float td = (float)OUT_DIM / (float)NCOLS;  // 0.0625
    float bs = boost_strength[0];
    g_bf[k] = expf((td - duty_cycle[k]) * bs);
#if __CUDA_ARCH__ >= 900
    cudaTriggerProgrammaticLaunchCompletion();
#endif
}

__global__ void __launch_bounds__(256)
dkw_kernel(const float* __restrict__ x, float* __restrict__ out) {
    __shared__ float sx[NSTAGE4 * 4];    // raw x window span
    __shared__ float sb[NSTAGE4 * 4];    // bf window span
    __shared__ int   s_bj[WPB];

    const int tid = threadIdx.x;
    const int b = blockIdx.x >> 4;        // batch row
    const int w = blockIdx.x & 15;        // window-block within row

    const size_t rowoff = (size_t)b * NCOLS;
    const int W0 = 3840 * w;              // window span start (16B aligned)
    const int O0 = 4096 * w;              // output chunk span start
    // Over-fetch proof: W0 + 3856 <= 3840*15 + 3856 = 61456 < 65536.

    const float4* xw4 = reinterpret_cast<const float4*>(x + rowoff + W0);
    const float4* bf4 = reinterpret_cast<const float4*>(g_bf + W0);
    float4* sx4 = reinterpret_cast<float4*>(sx);
    float4* sb4 = reinterpret_cast<float4*>(sb);

    // ---- Async stage x window (issued before the PDL wait: prefetch overlap) ----
#pragma unroll
    for (int t = tid; t < NSTAGE4; t += WPB)
        __pipeline_memcpy_async(&sx4[t], &xw4[t], 16);
    __pipeline_commit();

#if __CUDA_ARCH__ >= 900
    cudaGridDependencySynchronize();      // g_bf ready (PDL)
#endif

    // ---- Async stage bf window ----
#pragma unroll
    for (int t = tid; t < NSTAGE4; t += WPB)
        __pipeline_memcpy_async(&sb4[t], &bf4[t], 16);
    __pipeline_commit();

    __pipeline_wait_prior(0);
    __syncthreads();

    // ---- Argmax over window [15*tid, 15*tid+16): both arrays stride-15, conflict-free ----
    const float* px = sx + 15 * tid;
    const float* pb = sb + 15 * tid;
    float best = -INFINITY;
    int bj = 0;
#pragma unroll
    for (int j = 0; j < DPC; ++j) {
        float v = px[j] * pb[j];
        if (v > best) { best = v; bj = j; }
    }
    s_bj[tid] = bj;
    __syncthreads();

    // ---- Output: coalesced re-read of x chunk (mostly L1/L2 hot) + mask + store ----
    const float4* xc4 = reinterpret_cast<const float4*>(x + rowoff + O0);
    float4* o4 = reinterpret_cast<float4*>(out + rowoff + O0);
#pragma unroll
    for (int q = 0; q < 4; ++q) {
        int f  = tid + WPB * q;           // float4 index 0..1023
        int c  = f >> 2;                  // window index within block
        int j0 = (f & 3) << 2;            // first j covered by this float4
        int bjc = s_bj[c];
        float4 xv = xc4[f];
        float4 v;
        v.x = (bjc == j0 + 0) ? xv.x : 0.0f;
        v.y = (bjc == j0 + 1) ? xv.y : 0.0f;
        v.z = (bjc == j0 + 2) ? xv.z : 0.0f;
        v.w = (bjc == j0 + 3) ? xv.w : 0.0f;
        o4[f] = v;
    }
}

extern "C" void kernel_launch(void* const* d_in, const int* in_sizes, int n_in,
                              void* d_out, int out_size) {
    const float* x  = (const float*)d_in[0];
    const float* dc = (const float*)d_in[1];
    const float* bs = (const float*)d_in[2];
    float* out = (float*)d_out;

    bf_kernel<<<NCOLS / 256, 256>>>(dc, bs);

    cudaLaunchConfig_t cfg = {};
    cfg.gridDim  = dim3(BATCH * (OUT_DIM / WPB), 1, 1);
    cfg.blockDim = dim3(WPB, 1, 1);
    cfg.dynamicSmemBytes = 0;
    cfg.stream = 0;
    cudaLaunchAttribute attr[1];
    attr[0].id = cudaLaunchAttributeProgrammaticStreamSerialization;
    attr[0].val.programmaticStreamSerializationAllowed = 1;
    cfg.attrs = attr;
    cfg.numAttrs = 1;
    cudaLaunchKernelEx(&cfg, dkw_kernel, x, out);
}